// round 6
// baseline (speedup 1.0000x reference)
#include <cuda_runtime.h>
#include <cstdint>

#define T_DIM 1024
#define B_DIM 4
#define E_DIM 1024
#define NBH   64
#define MROWS 4096

// ---------------- scratch ----------------
__device__ float g_Q  [NBH * T_DIM * 128];            // [qre*s | qim*s]
__device__ float g_K2 [NBH * T_DIM * 128];            // [kp | km]
__device__ float g_VT [NBH * 128 * T_DIM];            // [vre ; vim] transposed
__device__ float g_AT2[MROWS * 2048];                 // attn out augmented
__device__ float g_AWR[(size_t)NBH * T_DIM * T_DIM];  // raw scores 256MB
__device__ float g_VSUM[NBH * 128];
__device__ unsigned g_minU, g_maxU;

// ---------------- helpers ----------------
__device__ __forceinline__ unsigned encodeOrd(float f) {
    unsigned u = __float_as_uint(f);
    return (u & 0x80000000u) ? ~u : (u | 0x80000000u);
}
__device__ __forceinline__ float decodeOrd(unsigned u) {
    return (u & 0x80000000u) ? __uint_as_float(u & 0x7FFFFFFFu)
                             : __uint_as_float(~u);
}
__device__ __forceinline__ float tf32f(float f) {
    uint32_t r; asm("cvt.rna.tf32.f32 %0, %1;" : "=r"(r) : "f"(f));
    return __uint_as_float(r);
}
__device__ __forceinline__ void mma8(float* c, const uint32_t* a, const uint32_t* b) {
    asm volatile(
        "mma.sync.aligned.m16n8k8.row.col.f32.tf32.tf32.f32 "
        "{%0,%1,%2,%3}, {%4,%5,%6,%7}, {%8,%9}, {%0,%1,%2,%3};"
        : "+f"(c[0]), "+f"(c[1]), "+f"(c[2]), "+f"(c[3])
        : "r"(a[0]), "r"(a[1]), "r"(a[2]), "r"(a[3]), "r"(b[0]), "r"(b[1]));
}

__global__ void init_kernel() { g_minU = 0xFFFFFFFFu; g_maxU = 0u; }

// ---------------- mma.sync tf32 GEMM core ----------------
// C(128x128) = A(128xK) * B(128xK)^T, 256 threads, 8 warps (2x4), warp 64x32.
// Smem holds one KT=32 chunk in mma-fragment-permuted layout:
//   A[( (ki*8+mi)*32 + lane )*4 + v]   (m16k8 tile mi, k8 tile ki)
//   B[( (ki*16+ni)*32 + lane )*2 + v]  (n8k8 tile ni)
struct Smem2 { float A[4096]; float B[4096]; };

template<class LA, class LB>
__device__ __forceinline__ void gemm_core(const LA& la, const LB& lb, int nChunks,
                                          float (&acc)[4][4][4], Smem2& sm)
{
    const int tid  = threadIdx.x;
    const int lane = tid & 31;
    const int warp = tid >> 5;
    const int wmi = (warp >> 2) * 4;       // A m16-tile base
    const int wni = (warp & 3) * 4;        // B n8-tile base
    // producer mapping: thread -> row pr, float4-col base pc0 (4 float4s/matrix)
    const int pr  = tid >> 1;
    const int pc0 = (tid & 1) * 4;
    const int pmi = pr >> 4, prm = pr & 15, pg = prm & 7, phi = prm >> 3;
    const int pni = pr >> 3, png = pr & 7;

    float4 ra[4], rb[4];
    #pragma unroll
    for (int q = 0; q < 4; q++) { ra[q] = la(pr, pc0 + q); rb[q] = lb(pr, pc0 + q); }

    auto sts = [&]() {
        #pragma unroll
        for (int q = 0; q < 4; q++) {
            int c  = pc0 + q;          // float4-col within chunk, 0..7
            int ki = c >> 1;
            int kh = c & 1;
            {   // A: value slot v = 2*kh + phi ; lanes 4*pg + 0..3 (stride 4 floats)
                float* p = &sm.A[((ki * 8 + pmi) * 32 + 4 * pg) * 4 + kh * 2 + phi];
                p[0]  = tf32f(ra[q].x); p[4]  = tf32f(ra[q].y);
                p[8]  = tf32f(ra[q].z); p[12] = tf32f(ra[q].w);
            }
            {   // B: value slot v = kh ; lanes 4*png + 0..3 (stride 2 floats)
                float* p = &sm.B[((ki * 16 + pni) * 32 + 4 * png) * 2 + kh];
                p[0] = tf32f(rb[q].x); p[2] = tf32f(rb[q].y);
                p[4] = tf32f(rb[q].z); p[6] = tf32f(rb[q].w);
            }
        }
    };
    sts();
    __syncthreads();

    for (int ch = 0; ch < nChunks; ch++) {
        if (ch + 1 < nChunks) {
            #pragma unroll
            for (int q = 0; q < 4; q++) {
                ra[q] = la(pr, (ch + 1) * 8 + pc0 + q);
                rb[q] = lb(pr, (ch + 1) * 8 + pc0 + q);
            }
        }
        #pragma unroll
        for (int ki = 0; ki < 4; ki++) {
            uint32_t af[4][4], bf[4][2];
            #pragma unroll
            for (int i = 0; i < 4; i++) {
                const float4 v = *(const float4*)&sm.A[((ki * 8 + wmi + i) * 32 + lane) * 4];
                af[i][0] = __float_as_uint(v.x); af[i][1] = __float_as_uint(v.y);
                af[i][2] = __float_as_uint(v.z); af[i][3] = __float_as_uint(v.w);
            }
            #pragma unroll
            for (int j = 0; j < 4; j++) {
                const float2 v = *(const float2*)&sm.B[((ki * 16 + wni + j) * 32 + lane) * 2];
                bf[j][0] = __float_as_uint(v.x); bf[j][1] = __float_as_uint(v.y);
            }
            #pragma unroll
            for (int i = 0; i < 4; i++)
                #pragma unroll
                for (int j = 0; j < 4; j++)
                    mma8(acc[i][j], af[i], bf[j]);
        }
        if (ch + 1 < nChunks) {
            __syncthreads();
            sts();
            __syncthreads();
        }
    }
}

// fragment element coordinates: rows r0, r0+8 ; cols c, c+1 (c even)
#define FRAG_COORDS \
    const int lane = threadIdx.x & 31; \
    const int warp = threadIdx.x >> 5; \
    const int wm = (warp >> 2) * 64, wn = (warp & 3) * 32; \
    const int g = lane >> 2, tg = lane & 3;

// ---------------- K1: in-projection (augmented complex GEMM) -------------
__global__ void __launch_bounds__(256) proj_kernel(
    const float* __restrict__ xre, const float* __restrict__ xim,
    const float* __restrict__ wre, const float* __restrict__ wim,
    const float* __restrict__ Bre, const float* __restrict__ Bim)
{
    __shared__ Smem2 sm;
    float acc[4][4][4] = {};
    const int m0 = blockIdx.y << 7;
    const int n0 = blockIdx.x << 7;   // augmented col base
    auto la = [&](int row, int f4) -> float4 {
        int k = f4 << 2;
        const float* s = (k < 1024) ? (xre + (size_t)(m0 + row) * 1024 + k)
                                    : (xim + (size_t)(m0 + row) * 1024 + (k - 1024));
        return *(const float4*)s;
    };
    auto lb = [&](int row, int f4) -> float4 {
        int naug = n0 + row; int n = naug >> 1; int k = f4 << 2;
        float4 v;
        if ((naug & 1) == 0) {
            if (k < 1024) v = *(const float4*)(wre + (size_t)n * 1024 + k);
            else { v = *(const float4*)(wim + (size_t)n * 1024 + k - 1024);
                   v.x = -v.x; v.y = -v.y; v.z = -v.z; v.w = -v.w; }
        } else {
            if (k < 1024) v = *(const float4*)(wim + (size_t)n * 1024 + k);
            else          v = *(const float4*)(wre + (size_t)n * 1024 + k - 1024);
        }
        return v;
    };
    gemm_core(la, lb, 64, acc, sm);

    FRAG_COORDS;
    #pragma unroll
    for (int i = 0; i < 4; i++) {
        #pragma unroll
        for (int j = 0; j < 4; j++) {
            int na = n0 + wn + j * 8 + 2 * tg;    // even
            int n = na >> 1;
            int sect = n >> 10, e = n & 1023;
            int bh_base = (e >> 6), d = e & 63;
            float bre = Bre[n], bim = Bim[n];
            #pragma unroll
            for (int rr = 0; rr < 2; rr++) {
                int m = m0 + wm + i * 16 + g + rr * 8;
                float re = acc[i][j][rr * 2 + 0] + bre;
                float im = acc[i][j][rr * 2 + 1] + bim;
                int t = m >> 2, b = m & 3;
                int bh = b * 16 + bh_base;
                if (sect == 0) {
                    int idx = (bh * 1024 + t) * 128 + d;
                    g_Q[idx] = re * 0.125f; g_Q[idx + 64] = im * 0.125f;
                } else if (sect == 1) {
                    int idx = (bh * 1024 + t) * 128 + d;
                    g_K2[idx] = re + im; g_K2[idx + 64] = re - im;
                } else {
                    int idx = (bh * 128 + d) * 1024 + t;
                    g_VT[idx] = re; g_VT[idx + 65536] = im;
                }
            }
        }
    }
}

// ---------------- K1b: per-head V column sums ----------------
__global__ void vsum_kernel() {
    int rowid = blockIdx.x * 8 + (threadIdx.x >> 5);   // 0..8191
    int lane = threadIdx.x & 31;
    const float* p = g_VT + (size_t)rowid * T_DIM;
    float s = 0.f;
    for (int t = lane; t < T_DIM; t += 32) s += p[t];
    #pragma unroll
    for (int o = 16; o; o >>= 1) s += __shfl_xor_sync(0xFFFFFFFFu, s, o);
    if (!lane) g_VSUM[rowid] = s;
}

// ---------------- K2: batched QK^T + global min/max ----------------
__global__ void __launch_bounds__(256) qk_kernel()
{
    __shared__ Smem2 sm;
    __shared__ unsigned sMin[8], sMax[8];
    float acc[4][4][4] = {};
    const int bh = blockIdx.z;
    const int m0 = blockIdx.y << 7, n0 = blockIdx.x << 7;
    const float* Qp = g_Q  + (size_t)bh * T_DIM * 128;
    const float* Kp = g_K2 + (size_t)bh * T_DIM * 128;
    auto la = [&](int row, int f4) -> float4 {
        return *(const float4*)(Qp + (size_t)(m0 + row) * 128 + (f4 << 2));
    };
    auto lb = [&](int row, int f4) -> float4 {
        return *(const float4*)(Kp + (size_t)(n0 + row) * 128 + (f4 << 2));
    };
    gemm_core(la, lb, 4, acc, sm);

    FRAG_COORDS;
    float* out = g_AWR + (size_t)bh * T_DIM * T_DIM;
    unsigned umin = 0xFFFFFFFFu, umax = 0u;
    #pragma unroll
    for (int i = 0; i < 4; i++) {
        #pragma unroll
        for (int j = 0; j < 4; j++) {
            int n = n0 + wn + j * 8 + 2 * tg;
            #pragma unroll
            for (int rr = 0; rr < 2; rr++) {
                int m = m0 + wm + i * 16 + g + rr * 8;
                float v0 = acc[i][j][rr * 2 + 0];
                float v1 = acc[i][j][rr * 2 + 1];
                *(float2*)(out + (size_t)m * T_DIM + n) = make_float2(v0, v1);
                unsigned e0 = encodeOrd(v0), e1 = encodeOrd(v1);
                umin = min(umin, min(e0, e1));
                umax = max(umax, max(e0, e1));
            }
        }
    }
    #pragma unroll
    for (int o = 16; o; o >>= 1) {
        umin = min(umin, __shfl_xor_sync(0xFFFFFFFFu, umin, o));
        umax = max(umax, __shfl_xor_sync(0xFFFFFFFFu, umax, o));
    }
    if (!lane) { sMin[warp] = umin; sMax[warp] = umax; }
    __syncthreads();
    if (threadIdx.x == 0) {
        umin = sMin[0]; umax = sMax[0];
        #pragma unroll
        for (int w = 1; w < 8; w++) { umin = min(umin, sMin[w]); umax = max(umax, sMax[w]); }
        atomicMin(&g_minU, umin);
        atomicMax(&g_maxU, umax);
    }
}

// ---------------- K3: AV with fused normalization ----------------
__global__ void __launch_bounds__(256) attn_kernel()
{
    __shared__ Smem2 sm;
    float acc[4][4][4] = {};
    const int m0 = blockIdx.x << 7;
    const int bh = blockIdx.y;
    const float* A = g_AWR + ((size_t)bh << 20);
    const float* V = g_VT + (size_t)bh * 128 * T_DIM;
    auto la = [&](int row, int f4) -> float4 {
        return *(const float4*)(A + (size_t)(m0 + row) * 1024 + (f4 << 2));
    };
    auto lb = [&](int row, int f4) -> float4 {
        return *(const float4*)(V + (size_t)row * 1024 + (f4 << 2));
    };
    gemm_core(la, lb, 32, acc, sm);

    FRAG_COORDS;
    float gmin = decodeOrd(g_minU);
    float gmax = decodeOrd(g_maxU);
    float inv = 1.0f / (gmax - gmin);
    int b = bh >> 4, h = bh & 15;
    #pragma unroll
    for (int i = 0; i < 4; i++) {
        #pragma unroll
        for (int j = 0; j < 4; j++) {
            int dd = wn + j * 8 + 2 * tg;     // even, 0..126
            float vs0 = g_VSUM[bh * 128 + dd];
            float vs1 = g_VSUM[bh * 128 + dd + 1];
            int col0 = (dd < 64)     ? h * 64 + dd     : 1024 + h * 64 + dd - 64;
            int col1 = (dd + 1 < 64) ? h * 64 + dd + 1 : 1024 + h * 64 + dd + 1 - 64;
            #pragma unroll
            for (int rr = 0; rr < 2; rr++) {
                int t = m0 + wm + i * 16 + g + rr * 8;
                int m2 = t * B_DIM + b;
                float v0 = (acc[i][j][rr * 2 + 0] - gmin * vs0) * inv;
                float v1 = (acc[i][j][rr * 2 + 1] - gmin * vs1) * inv;
                g_AT2[(size_t)m2 * 2048 + col0] = v0;
                g_AT2[(size_t)m2 * 2048 + col1] = v1;
            }
        }
    }
}

// ---------------- K4: head-averaged attention map ----------------
__global__ void avg_kernel(float* __restrict__ out)
{
    int idx = blockIdx.x * blockDim.x + threadIdx.x;
    int b = idx >> 20;
    int off = idx & 0xFFFFF;
    const float* base = g_AWR + ((size_t)b << 24) + off;
    float s = 0.f;
    #pragma unroll
    for (int h = 0; h < 16; h++) s += base[(size_t)h << 20];
    float gmin = decodeOrd(g_minU);
    float gmax = decodeOrd(g_maxU);
    out[idx] = (s * (1.0f / 16.0f) - gmin) / (gmax - gmin);
}

// ---------------- K5: out-projection ----------------
__global__ void __launch_bounds__(256) outproj_kernel(
    const float* __restrict__ owre, const float* __restrict__ owim,
    const float* __restrict__ obre, const float* __restrict__ obim,
    float* __restrict__ outRe, float* __restrict__ outIm)
{
    __shared__ Smem2 sm;
    float acc[4][4][4] = {};
    const int m0 = blockIdx.y << 7;
    const int n0 = blockIdx.x << 7;   // augmented (0..2047)
    auto la = [&](int row, int f4) -> float4 {
        return *(const float4*)(g_AT2 + (size_t)(m0 + row) * 2048 + (f4 << 2));
    };
    auto lb = [&](int row, int f4) -> float4 {
        int naug = n0 + row; int n = naug >> 1; int k = f4 << 2;
        float4 v;
        if ((naug & 1) == 0) {
            if (k < 1024) v = *(const float4*)(owre + (size_t)n * 1024 + k);
            else { v = *(const float4*)(owim + (size_t)n * 1024 + k - 1024);
                   v.x = -v.x; v.y = -v.y; v.z = -v.z; v.w = -v.w; }
        } else {
            if (k < 1024) v = *(const float4*)(owim + (size_t)n * 1024 + k);
            else          v = *(const float4*)(owre + (size_t)n * 1024 + k - 1024);
        }
        return v;
    };
    gemm_core(la, lb, 64, acc, sm);

    FRAG_COORDS;
    #pragma unroll
    for (int i = 0; i < 4; i++) {
        #pragma unroll
        for (int j = 0; j < 4; j++) {
            int na = n0 + wn + j * 8 + 2 * tg;
            int n = na >> 1;
            float bre = obre[n], bim = obim[n];
            #pragma unroll
            for (int rr = 0; rr < 2; rr++) {
                int m = m0 + wm + i * 16 + g + rr * 8;
                outRe[(size_t)m * 1024 + n] = acc[i][j][rr * 2 + 0] + bre;
                outIm[(size_t)m * 1024 + n] = acc[i][j][rr * 2 + 1] + bim;
            }
        }
    }
}

// ---------------- launch ----------------
extern "C" void kernel_launch(void* const* d_in, const int* in_sizes, int n_in,
                              void* d_out, int out_size)
{
    const float* x_re  = (const float*)d_in[0];
    const float* x_im  = (const float*)d_in[1];
    const float* w_re  = (const float*)d_in[2];
    const float* w_im  = (const float*)d_in[3];
    const float* b_re  = (const float*)d_in[4];
    const float* b_im  = (const float*)d_in[5];
    const float* ow_re = (const float*)d_in[6];
    const float* ow_im = (const float*)d_in[7];
    const float* ob_re = (const float*)d_in[8];
    const float* ob_im = (const float*)d_in[9];

    float* out_re = (float*)d_out;
    float* out_im = out_re + (size_t)MROWS * E_DIM;
    float* aw_avg = out_im + (size_t)MROWS * E_DIM;

    init_kernel<<<1, 1>>>();
    proj_kernel<<<dim3(48, 32), 256>>>(x_re, x_im, w_re, w_im, b_re, b_im);
    vsum_kernel<<<1024, 256>>>();
    qk_kernel<<<dim3(8, 8, 64), 256>>>();
    attn_kernel<<<dim3(8, 64), 256>>>();
    avg_kernel<<<(B_DIM * T_DIM * T_DIM) / 256, 256>>>(aw_avg);
    outproj_kernel<<<dim3(16, 32), 256>>>(ow_re, ow_im, ob_re, ob_im,
                                          out_re, out_im);
}

// round 13
// speedup vs baseline: 2.1524x; 2.1524x over previous
#include <cuda_runtime.h>
#include <cstdint>

#define T_DIM 1024
#define B_DIM 4
#define E_DIM 1024
#define NBH   64
#define MROWS 4096

// ---------------- scratch ----------------
__device__ float g_WB [6144 * 2048];                  // packed aug in-proj W (tf32)
__device__ float g_OWB[2048 * 2048];                  // packed aug out-proj W (tf32)
__device__ float g_Q  [NBH * T_DIM * 128];            // [qre*s | qim*s] (tf32)
__device__ float g_K2 [NBH * T_DIM * 128];            // [kp | km] (tf32)
__device__ float g_VT [NBH * 128 * T_DIM];            // [vre ; vim] transposed (tf32)
__device__ float g_AT2[MROWS * 2048];                 // attn out augmented (tf32)
__device__ float g_AWR[(size_t)NBH * T_DIM * T_DIM];  // raw scores fp32 256MB
__device__ float g_VSUM[NBH * 128];
__device__ unsigned g_minU, g_maxU;

// ---------------- helpers ----------------
__device__ __forceinline__ unsigned encodeOrd(float f) {
    unsigned u = __float_as_uint(f);
    return (u & 0x80000000u) ? ~u : (u | 0x80000000u);
}
__device__ __forceinline__ float decodeOrd(unsigned u) {
    return (u & 0x80000000u) ? __uint_as_float(u & 0x7FFFFFFFu)
                             : __uint_as_float(~u);
}
__device__ __forceinline__ float tf32f(float f) {
    uint32_t r; asm("cvt.rna.tf32.f32 %0, %1;" : "=r"(r) : "f"(f));
    return __uint_as_float(r);
}
__device__ __forceinline__ uint32_t smem_u32(const void* p) {
    uint32_t a;
    asm("{ .reg .u64 t; cvta.to.shared.u64 t, %1; cvt.u32.u64 %0, t; }"
        : "=r"(a) : "l"(p));
    return a;
}
__device__ __forceinline__ void mma8(float* c, const uint32_t* a, const uint32_t* b) {
    asm volatile(
        "mma.sync.aligned.m16n8k8.row.col.f32.tf32.tf32.f32 "
        "{%0,%1,%2,%3}, {%4,%5,%6,%7}, {%8,%9}, {%0,%1,%2,%3};"
        : "+f"(c[0]), "+f"(c[1]), "+f"(c[2]), "+f"(c[3])
        : "r"(a[0]), "r"(a[1]), "r"(a[2]), "r"(a[3]), "r"(b[0]), "r"(b[1]));
}
__device__ __forceinline__ void cpa16(uint32_t dst, const void* src) {
    asm volatile("cp.async.cg.shared.global [%0], [%1], 16;"
                 :: "r"(dst), "l"(src) : "memory");
}
__device__ __forceinline__ void cpa_commit() {
    asm volatile("cp.async.commit_group;" ::: "memory");
}
template<int N> __device__ __forceinline__ void cpa_wait() {
    asm volatile("cp.async.wait_group %0;" :: "n"(N) : "memory");
}

__global__ void init_kernel() { g_minU = 0xFFFFFFFFu; g_maxU = 0u; }

// ---------------- cp.async 3-stage tf32 GEMM core ----------------
// C(128 x NT) = A(128 x K) * B(NT x K)^T ; KT=32 per chunk.
// Smem per stage: A 128 rows x 128B, B NT rows x 128B; float4-col XOR swizzle.
template<int NT, int NTHR, bool CVTA, class LA, class LB>
__device__ __forceinline__ void gemm_cp(const LA& la, const LB& lb, int nChunks,
                                        float (&acc)[4][4][4], float* smem)
{
    const int tid  = threadIdx.x;
    const int lane = tid & 31;
    const int warp = tid >> 5;
    const int g = lane >> 2, tg = lane & 3;
    const int wm = (NTHR == 512) ? (warp >> 3) * 64 : (warp >> 2) * 64;
    const int wn = (NTHR == 512) ? (warp & 7) * 32  : (warp & 3) * 32;
    constexpr int STAGEF = (128 + NT) * 32;      // floats per stage
    const uint32_t sb = smem_u32(smem);

    auto produce = [&](int ch) {
        uint32_t aB = sb + (uint32_t)(ch % 3) * (STAGEF * 4);
        uint32_t bB = aB + 128 * 128;
        #pragma unroll
        for (int t = 0; t < 1024 / NTHR; t++) {
            int idx = tid + t * NTHR;
            int row = idx >> 3, c4 = idx & 7;
            cpa16(aB + (uint32_t)((row * 8 + (c4 ^ (row & 7))) * 16),
                  la(row, ch * 8 + c4));
        }
        #pragma unroll
        for (int t = 0; t < NT * 8 / NTHR; t++) {
            int idx = tid + t * NTHR;
            int row = idx >> 3, c4 = idx & 7;
            cpa16(bB + (uint32_t)((row * 8 + (c4 ^ (row & 7))) * 16),
                  lb(row, ch * 8 + c4));
        }
    };

    produce(0); cpa_commit();
    if (nChunks > 1) produce(1);
    cpa_commit();

    for (int ch = 0; ch < nChunks; ch++) {
        cpa_wait<1>();
        __syncthreads();
        const float* As = smem + (ch % 3) * STAGEF;
        const float* Bs = As + 128 * 32;
        if (ch + 2 < nChunks) produce(ch + 2);
        cpa_commit();
        #pragma unroll
        for (int ki = 0; ki < 4; ki++) {
            const int x0 = ((2 * ki)     ^ g) * 4 + tg;
            const int x1 = ((2 * ki + 1) ^ g) * 4 + tg;
            uint32_t af[4][4], bf[4][2];
            #pragma unroll
            for (int i = 0; i < 4; i++) {
                const float* pm  = As + (wm + i * 16 + g) * 32;
                const float* pm8 = pm + 8 * 32;
                float v0 = pm[x0], v1 = pm8[x0], v2 = pm[x1], v3 = pm8[x1];
                if (CVTA) { v0 = tf32f(v0); v1 = tf32f(v1);
                            v2 = tf32f(v2); v3 = tf32f(v3); }
                af[i][0] = __float_as_uint(v0); af[i][1] = __float_as_uint(v1);
                af[i][2] = __float_as_uint(v2); af[i][3] = __float_as_uint(v3);
            }
            #pragma unroll
            for (int j = 0; j < 4; j++) {
                const float* pn = Bs + (wn + j * 8 + g) * 32;
                bf[j][0] = __float_as_uint(pn[x0]);
                bf[j][1] = __float_as_uint(pn[x1]);
            }
            #pragma unroll
            for (int i = 0; i < 4; i++)
                #pragma unroll
                for (int j = 0; j < 4; j++)
                    mma8(acc[i][j], af[i], bf[j]);
        }
    }
}

#define FRAG_512 \
    const int lane = threadIdx.x & 31; const int warp = threadIdx.x >> 5; \
    const int wm = (warp >> 3) * 64, wn = (warp & 7) * 32; \
    const int g = lane >> 2, tg = lane & 3;
#define FRAG_256 \
    const int lane = threadIdx.x & 31; const int warp = threadIdx.x >> 5; \
    const int wm = (warp >> 2) * 64, wn = (warp & 3) * 32; \
    const int g = lane >> 2, tg = lane & 3;

// ---------------- weight packing (augmented + tf32-rounded) ----------------
__global__ void pack_w_kernel(const float* __restrict__ wre,
                              const float* __restrict__ wim) {
    int i = blockIdx.x * 256 + threadIdx.x;     // float4 index over 6144*512
    int row = i >> 9, c4 = i & 511;
    int n = row >> 1, p = row & 1;
    int k = c4 << 2;
    float4 v;
    if (p == 0) {
        if (k < 1024) v = *(const float4*)(wre + (size_t)n * 1024 + k);
        else { v = *(const float4*)(wim + (size_t)n * 1024 + k - 1024);
               v.x = -v.x; v.y = -v.y; v.z = -v.z; v.w = -v.w; }
    } else {
        if (k < 1024) v = *(const float4*)(wim + (size_t)n * 1024 + k);
        else          v = *(const float4*)(wre + (size_t)n * 1024 + k - 1024);
    }
    v.x = tf32f(v.x); v.y = tf32f(v.y); v.z = tf32f(v.z); v.w = tf32f(v.w);
    *(float4*)(g_WB + (size_t)i * 4) = v;
}
__global__ void pack_ow_kernel(const float* __restrict__ wre,
                               const float* __restrict__ wim) {
    int i = blockIdx.x * 256 + threadIdx.x;     // float4 index over 2048*512
    int row = i >> 9, c4 = i & 511;
    int n = row >> 1, p = row & 1;
    int k = c4 << 2;
    float4 v;
    if (p == 0) {
        if (k < 1024) v = *(const float4*)(wre + (size_t)n * 1024 + k);
        else { v = *(const float4*)(wim + (size_t)n * 1024 + k - 1024);
               v.x = -v.x; v.y = -v.y; v.z = -v.z; v.w = -v.w; }
    } else {
        if (k < 1024) v = *(const float4*)(wim + (size_t)n * 1024 + k);
        else          v = *(const float4*)(wre + (size_t)n * 1024 + k - 1024);
    }
    v.x = tf32f(v.x); v.y = tf32f(v.y); v.z = tf32f(v.z); v.w = tf32f(v.w);
    *(float4*)(g_OWB + (size_t)i * 4) = v;
}

// ---------------- K1: in-projection (128x256 tiles, 512 thr) ----------------
__global__ void __launch_bounds__(512, 1) proj_kernel(
    const float* __restrict__ xre, const float* __restrict__ xim,
    const float* __restrict__ Bre, const float* __restrict__ Bim)
{
    extern __shared__ float smem[];
    float acc[4][4][4] = {};
    const int m0 = blockIdx.y << 7;
    const int n0 = blockIdx.x << 8;
    auto la = [&](int row, int f4) -> const void* {
        int k = f4 << 2;
        return (k < 1024) ? (const void*)(xre + (size_t)(m0 + row) * 1024 + k)
                          : (const void*)(xim + (size_t)(m0 + row) * 1024 + (k - 1024));
    };
    auto lb = [&](int row, int f4) -> const void* {
        return (const void*)(g_WB + (size_t)(n0 + row) * 2048 + (f4 << 2));
    };
    gemm_cp<256, 512, true>(la, lb, 64, acc, smem);

    FRAG_512;
    #pragma unroll
    for (int i = 0; i < 4; i++) {
        #pragma unroll
        for (int j = 0; j < 4; j++) {
            int na = n0 + wn + j * 8 + 2 * tg;    // even
            int n = na >> 1;
            int sect = n >> 10, e = n & 1023;
            int bh_base = (e >> 6), d = e & 63;
            float bre = Bre[n], bim = Bim[n];
            #pragma unroll
            for (int rr = 0; rr < 2; rr++) {
                int m = m0 + wm + i * 16 + g + rr * 8;
                float re = acc[i][j][rr * 2 + 0] + bre;
                float im = acc[i][j][rr * 2 + 1] + bim;
                int t = m >> 2, b = m & 3;
                int bh = b * 16 + bh_base;
                if (sect == 0) {
                    int idx = (bh * 1024 + t) * 128 + d;
                    g_Q[idx] = tf32f(re * 0.125f); g_Q[idx + 64] = tf32f(im * 0.125f);
                } else if (sect == 1) {
                    int idx = (bh * 1024 + t) * 128 + d;
                    g_K2[idx] = tf32f(re + im); g_K2[idx + 64] = tf32f(re - im);
                } else {
                    int idx = (bh * 128 + d) * 1024 + t;
                    g_VT[idx] = tf32f(re); g_VT[idx + 65536] = tf32f(im);
                }
            }
        }
    }
}

// ---------------- K1b: per-head V column sums ----------------
__global__ void vsum_kernel() {
    int rowid = blockIdx.x * 8 + (threadIdx.x >> 5);   // 0..8191
    int lane = threadIdx.x & 31;
    const float* p = g_VT + (size_t)rowid * T_DIM;
    float s = 0.f;
    for (int t = lane; t < T_DIM; t += 32) s += p[t];
    #pragma unroll
    for (int o = 16; o; o >>= 1) s += __shfl_xor_sync(0xFFFFFFFFu, s, o);
    if (!lane) g_VSUM[rowid] = s;
}

// ---------------- K2: batched QK^T + global min/max (128x128, 256 thr) -----
__global__ void __launch_bounds__(256, 2) qk_kernel()
{
    extern __shared__ float smem[];
    __shared__ unsigned sMin[8], sMax[8];
    float acc[4][4][4] = {};
    const int bh = blockIdx.z;
    const int m0 = blockIdx.y << 7, n0 = blockIdx.x << 7;
    const float* Qp = g_Q  + (size_t)bh * T_DIM * 128;
    const float* Kp = g_K2 + (size_t)bh * T_DIM * 128;
    auto la = [&](int row, int f4) -> const void* {
        return (const void*)(Qp + (size_t)(m0 + row) * 128 + (f4 << 2));
    };
    auto lb = [&](int row, int f4) -> const void* {
        return (const void*)(Kp + (size_t)(n0 + row) * 128 + (f4 << 2));
    };
    gemm_cp<128, 256, false>(la, lb, 4, acc, smem);

    FRAG_256;
    float* out = g_AWR + (size_t)bh * T_DIM * T_DIM;
    unsigned umin = 0xFFFFFFFFu, umax = 0u;
    #pragma unroll
    for (int i = 0; i < 4; i++) {
        #pragma unroll
        for (int j = 0; j < 4; j++) {
            int n = n0 + wn + j * 8 + 2 * tg;
            #pragma unroll
            for (int rr = 0; rr < 2; rr++) {
                int m = m0 + wm + i * 16 + g + rr * 8;
                float v0 = acc[i][j][rr * 2 + 0];
                float v1 = acc[i][j][rr * 2 + 1];
                *(float2*)(out + (size_t)m * T_DIM + n) = make_float2(v0, v1);
                unsigned e0 = encodeOrd(v0), e1 = encodeOrd(v1);
                umin = min(umin, min(e0, e1));
                umax = max(umax, max(e0, e1));
            }
        }
    }
    #pragma unroll
    for (int o = 16; o; o >>= 1) {
        umin = min(umin, __shfl_xor_sync(0xFFFFFFFFu, umin, o));
        umax = max(umax, __shfl_xor_sync(0xFFFFFFFFu, umax, o));
    }
    if (!lane) { sMin[warp] = umin; sMax[warp] = umax; }
    __syncthreads();
    if (threadIdx.x == 0) {
        umin = sMin[0]; umax = sMax[0];
        #pragma unroll
        for (int w = 1; w < 8; w++) { umin = min(umin, sMin[w]); umax = max(umax, sMax[w]); }
        atomicMin(&g_minU, umin);
        atomicMax(&g_maxU, umax);
    }
}

// ---------------- K3: AV with fused normalization (128x128, 256 thr) -------
__global__ void __launch_bounds__(256, 2) attn_kernel()
{
    extern __shared__ float smem[];
    float acc[4][4][4] = {};
    const int m0 = blockIdx.x << 7;
    const int bh = blockIdx.y;
    const float* A = g_AWR + ((size_t)bh << 20);
    const float* V = g_VT + (size_t)bh * 128 * T_DIM;
    auto la = [&](int row, int f4) -> const void* {
        return (const void*)(A + (size_t)(m0 + row) * 1024 + (f4 << 2));
    };
    auto lb = [&](int row, int f4) -> const void* {
        return (const void*)(V + (size_t)row * 1024 + (f4 << 2));
    };
    gemm_cp<128, 256, true>(la, lb, 32, acc, smem);

    FRAG_256;
    float gmin = decodeOrd(g_minU);
    float gmax = decodeOrd(g_maxU);
    float inv = 1.0f / (gmax - gmin);
    int b = bh >> 4, h = bh & 15;
    #pragma unroll
    for (int i = 0; i < 4; i++) {
        #pragma unroll
        for (int j = 0; j < 4; j++) {
            int dd = wn + j * 8 + 2 * tg;     // even, 0..126
            float vs0 = g_VSUM[bh * 128 + dd];
            float vs1 = g_VSUM[bh * 128 + dd + 1];
            int col0 = (dd < 64)     ? h * 64 + dd     : 1024 + h * 64 + dd - 64;
            int col1 = (dd + 1 < 64) ? h * 64 + dd + 1 : 1024 + h * 64 + dd + 1 - 64;
            #pragma unroll
            for (int rr = 0; rr < 2; rr++) {
                int t = m0 + wm + i * 16 + g + rr * 8;
                int m2 = t * B_DIM + b;
                float v0 = (acc[i][j][rr * 2 + 0] - gmin * vs0) * inv;
                float v1 = (acc[i][j][rr * 2 + 1] - gmin * vs1) * inv;
                g_AT2[(size_t)m2 * 2048 + col0] = tf32f(v0);
                g_AT2[(size_t)m2 * 2048 + col1] = tf32f(v1);
            }
        }
    }
}

// ---------------- K4: head-averaged attention map ----------------
__global__ void avg_kernel(float* __restrict__ out)
{
    int idx = blockIdx.x * blockDim.x + threadIdx.x;
    int b = idx >> 20;
    int off = idx & 0xFFFFF;
    const float* base = g_AWR + ((size_t)b << 24) + off;
    float s = 0.f;
    #pragma unroll
    for (int h = 0; h < 16; h++) s += base[(size_t)h << 20];
    float gmin = decodeOrd(g_minU);
    float gmax = decodeOrd(g_maxU);
    out[idx] = (s * (1.0f / 16.0f) - gmin) / (gmax - gmin);
}

// ---------------- K5: out-projection (128x256, 512 thr) ----------------
__global__ void __launch_bounds__(512, 1) outproj_kernel(
    const float* __restrict__ obre, const float* __restrict__ obim,
    float* __restrict__ outRe, float* __restrict__ outIm)
{
    extern __shared__ float smem[];
    float acc[4][4][4] = {};
    const int m0 = blockIdx.y << 7;
    const int n0 = blockIdx.x << 8;   // augmented (0..2047)
    auto la = [&](int row, int f4) -> const void* {
        return (const void*)(g_AT2 + (size_t)(m0 + row) * 2048 + (f4 << 2));
    };
    auto lb = [&](int row, int f4) -> const void* {
        return (const void*)(g_OWB + (size_t)(n0 + row) * 2048 + (f4 << 2));
    };
    gemm_cp<256, 512, false>(la, lb, 64, acc, smem);

    FRAG_512;
    #pragma unroll
    for (int i = 0; i < 4; i++) {
        #pragma unroll
        for (int j = 0; j < 4; j++) {
            int na = n0 + wn + j * 8 + 2 * tg;
            int n = na >> 1;
            float bre = obre[n], bim = obim[n];
            #pragma unroll
            for (int rr = 0; rr < 2; rr++) {
                int m = m0 + wm + i * 16 + g + rr * 8;
                outRe[(size_t)m * 1024 + n] = acc[i][j][rr * 2 + 0] + bre;
                outIm[(size_t)m * 1024 + n] = acc[i][j][rr * 2 + 1] + bim;
            }
        }
    }
}

// ---------------- launch ----------------
#define SMEM_BIG (3 * (128 + 256) * 128)   // 147456
#define SMEM_SML (3 * (128 + 128) * 128)   // 98304

extern "C" void kernel_launch(void* const* d_in, const int* in_sizes, int n_in,
                              void* d_out, int out_size)
{
    const float* x_re  = (const float*)d_in[0];
    const float* x_im  = (const float*)d_in[1];
    const float* w_re  = (const float*)d_in[2];
    const float* w_im  = (const float*)d_in[3];
    const float* b_re  = (const float*)d_in[4];
    const float* b_im  = (const float*)d_in[5];
    const float* ow_re = (const float*)d_in[6];
    const float* ow_im = (const float*)d_in[7];
    const float* ob_re = (const float*)d_in[8];
    const float* ob_im = (const float*)d_in[9];

    float* out_re = (float*)d_out;
    float* out_im = out_re + (size_t)MROWS * E_DIM;
    float* aw_avg = out_im + (size_t)MROWS * E_DIM;

    cudaFuncSetAttribute(proj_kernel,    cudaFuncAttributeMaxDynamicSharedMemorySize, SMEM_BIG);
    cudaFuncSetAttribute(outproj_kernel, cudaFuncAttributeMaxDynamicSharedMemorySize, SMEM_BIG);
    cudaFuncSetAttribute(qk_kernel,      cudaFuncAttributeMaxDynamicSharedMemorySize, SMEM_SML);
    cudaFuncSetAttribute(attn_kernel,    cudaFuncAttributeMaxDynamicSharedMemorySize, SMEM_SML);

    init_kernel<<<1, 1>>>();
    pack_w_kernel <<<12288, 256>>>(w_re, w_im);
    pack_ow_kernel<<<4096, 256>>>(ow_re, ow_im);

    proj_kernel<<<dim3(24, 32), 512, SMEM_BIG>>>(x_re, x_im, b_re, b_im);
    vsum_kernel<<<1024, 256>>>();
    qk_kernel<<<dim3(8, 8, 64), 256, SMEM_SML>>>();
    attn_kernel<<<dim3(8, 64), 256, SMEM_SML>>>();
    avg_kernel<<<(B_DIM * T_DIM * T_DIM) / 256, 256>>>(aw_avg);
    outproj_kernel<<<dim3(8, 32), 512, SMEM_BIG>>>(ob_re, ob_im, out_re, out_im);
}

// round 16
// speedup vs baseline: 2.5044x; 1.1635x over previous
#include <cuda_runtime.h>
#include <cstdint>

#define T_DIM 1024
#define B_DIM 4
#define E_DIM 1024
#define NBH   64
#define MROWS 4096

// ---------------- scratch ----------------
__device__ float g_XA [MROWS * 2048];                 // packed aug X (tf32) 32MB
__device__ float g_WB [6144 * 2048];                  // packed aug in-proj W (tf32)
__device__ float g_OWB[2048 * 2048];                  // packed aug out-proj W (tf32)
__device__ float g_Q  [NBH * T_DIM * 128];            // [qre*s | qim*s] (tf32)
__device__ float g_K2 [NBH * T_DIM * 128];            // [kp | km] (tf32)
__device__ float g_VT [NBH * 128 * T_DIM];            // [vre ; vim] transposed (tf32)
__device__ float g_AT2[MROWS * 2048];                 // attn out augmented (tf32)
__device__ float g_AWR[(size_t)NBH * T_DIM * T_DIM];  // raw scores tf32-rounded 256MB
__device__ float g_VSUM[NBH * 128];
__device__ unsigned g_minU, g_maxU;

// ---------------- helpers ----------------
__device__ __forceinline__ unsigned encodeOrd(float f) {
    unsigned u = __float_as_uint(f);
    return (u & 0x80000000u) ? ~u : (u | 0x80000000u);
}
__device__ __forceinline__ float decodeOrd(unsigned u) {
    return (u & 0x80000000u) ? __uint_as_float(u & 0x7FFFFFFFu)
                             : __uint_as_float(~u);
}
__device__ __forceinline__ float tf32f(float f) {
    uint32_t r; asm("cvt.rna.tf32.f32 %0, %1;" : "=r"(r) : "f"(f));
    return __uint_as_float(r);
}
__device__ __forceinline__ uint32_t smem_u32(const void* p) {
    uint32_t a;
    asm("{ .reg .u64 t; cvta.to.shared.u64 t, %1; cvt.u32.u64 %0, t; }"
        : "=r"(a) : "l"(p));
    return a;
}
__device__ __forceinline__ void mma8(float* c, const uint32_t* a, const uint32_t* b) {
    asm volatile(
        "mma.sync.aligned.m16n8k8.row.col.f32.tf32.tf32.f32 "
        "{%0,%1,%2,%3}, {%4,%5,%6,%7}, {%8,%9}, {%0,%1,%2,%3};"
        : "+f"(c[0]), "+f"(c[1]), "+f"(c[2]), "+f"(c[3])
        : "r"(a[0]), "r"(a[1]), "r"(a[2]), "r"(a[3]), "r"(b[0]), "r"(b[1]));
}
__device__ __forceinline__ void cpa16(uint32_t dst, const void* src) {
    asm volatile("cp.async.cg.shared.global [%0], [%1], 16;"
                 :: "r"(dst), "l"(src) : "memory");
}
__device__ __forceinline__ void cpa_commit() {
    asm volatile("cp.async.commit_group;" ::: "memory");
}
template<int N> __device__ __forceinline__ void cpa_wait() {
    asm volatile("cp.async.wait_group %0;" :: "n"(N) : "memory");
}

__global__ void init_kernel() { g_minU = 0xFFFFFFFFu; g_maxU = 0u; }

// ---------------- cp.async 3-stage tf32 GEMM core ----------------
// C(128 x 128) = A(128 x K) * B(128 x K)^T ; KT=32 per chunk; 256 threads.
// Smem per stage: (128+128) rows x 128B; float4-col XOR swizzle.
template<class LA, class LB>
__device__ __forceinline__ void gemm_cp(const LA& la, const LB& lb, int nChunks,
                                        float (&acc)[4][4][4], float* smem)
{
    const int tid  = threadIdx.x;
    const int lane = tid & 31;
    const int warp = tid >> 5;
    const int g = lane >> 2, tg = lane & 3;
    const int wm = (warp >> 2) * 64;
    const int wn = (warp & 3) * 32;
    constexpr int STAGEF = 256 * 32;             // floats per stage
    const uint32_t sb = smem_u32(smem);

    auto produce = [&](int ch) {
        uint32_t aB = sb + (uint32_t)(ch % 3) * (STAGEF * 4);
        uint32_t bB = aB + 128 * 128;
        #pragma unroll
        for (int t = 0; t < 4; t++) {
            int idx = tid + t * 256;
            int row = idx >> 3, c4 = idx & 7;
            cpa16(aB + (uint32_t)((row * 8 + (c4 ^ (row & 7))) * 16),
                  la(row, ch * 8 + c4));
        }
        #pragma unroll
        for (int t = 0; t < 4; t++) {
            int idx = tid + t * 256;
            int row = idx >> 3, c4 = idx & 7;
            cpa16(bB + (uint32_t)((row * 8 + (c4 ^ (row & 7))) * 16),
                  lb(row, ch * 8 + c4));
        }
    };

    produce(0); cpa_commit();
    if (nChunks > 1) produce(1);
    cpa_commit();

    for (int ch = 0; ch < nChunks; ch++) {
        cpa_wait<1>();
        __syncthreads();
        const float* As = smem + (ch % 3) * STAGEF;
        const float* Bs = As + 128 * 32;
        if (ch + 2 < nChunks) produce(ch + 2);
        cpa_commit();
        #pragma unroll
        for (int ki = 0; ki < 4; ki++) {
            const int x0 = ((2 * ki)     ^ g) * 4 + tg;
            const int x1 = ((2 * ki + 1) ^ g) * 4 + tg;
            uint32_t af[4][4], bf[4][2];
            #pragma unroll
            for (int i = 0; i < 4; i++) {
                const float* pm  = As + (wm + i * 16 + g) * 32;
                const float* pm8 = pm + 8 * 32;
                af[i][0] = __float_as_uint(pm[x0]);
                af[i][1] = __float_as_uint(pm8[x0]);
                af[i][2] = __float_as_uint(pm[x1]);
                af[i][3] = __float_as_uint(pm8[x1]);
            }
            #pragma unroll
            for (int j = 0; j < 4; j++) {
                const float* pn = Bs + (wn + j * 8 + g) * 32;
                bf[j][0] = __float_as_uint(pn[x0]);
                bf[j][1] = __float_as_uint(pn[x1]);
            }
            #pragma unroll
            for (int i = 0; i < 4; i++)
                #pragma unroll
                for (int j = 0; j < 4; j++)
                    mma8(acc[i][j], af[i], bf[j]);
        }
    }
}

#define FRAG_256 \
    const int lane = threadIdx.x & 31; const int warp = threadIdx.x >> 5; \
    const int wm = (warp >> 2) * 64, wn = (warp & 3) * 32; \
    const int g = lane >> 2, tg = lane & 3;

// ---------------- packing kernels (augmented + tf32-rounded) ---------------
__global__ void pack_x_kernel(const float* __restrict__ xre,
                              const float* __restrict__ xim) {
    int i = blockIdx.x * 256 + threadIdx.x;     // float4 index over 4096*512
    int m = i >> 9, c4 = i & 511;
    int k = c4 << 2;
    float4 v = (k < 1024) ? *(const float4*)(xre + (size_t)m * 1024 + k)
                          : *(const float4*)(xim + (size_t)m * 1024 + k - 1024);
    v.x = tf32f(v.x); v.y = tf32f(v.y); v.z = tf32f(v.z); v.w = tf32f(v.w);
    *(float4*)(g_XA + (size_t)i * 4) = v;
}
__global__ void pack_w_kernel(const float* __restrict__ wre,
                              const float* __restrict__ wim) {
    int i = blockIdx.x * 256 + threadIdx.x;     // float4 index over 6144*512
    int row = i >> 9, c4 = i & 511;
    int n = row >> 1, p = row & 1;
    int k = c4 << 2;
    float4 v;
    if (p == 0) {
        if (k < 1024) v = *(const float4*)(wre + (size_t)n * 1024 + k);
        else { v = *(const float4*)(wim + (size_t)n * 1024 + k - 1024);
               v.x = -v.x; v.y = -v.y; v.z = -v.z; v.w = -v.w; }
    } else {
        if (k < 1024) v = *(const float4*)(wim + (size_t)n * 1024 + k);
        else          v = *(const float4*)(wre + (size_t)n * 1024 + k - 1024);
    }
    v.x = tf32f(v.x); v.y = tf32f(v.y); v.z = tf32f(v.z); v.w = tf32f(v.w);
    *(float4*)(g_WB + (size_t)i * 4) = v;
}
__global__ void pack_ow_kernel(const float* __restrict__ wre,
                               const float* __restrict__ wim) {
    int i = blockIdx.x * 256 + threadIdx.x;     // float4 index over 2048*512
    int row = i >> 9, c4 = i & 511;
    int n = row >> 1, p = row & 1;
    int k = c4 << 2;
    float4 v;
    if (p == 0) {
        if (k < 1024) v = *(const float4*)(wre + (size_t)n * 1024 + k);
        else { v = *(const float4*)(wim + (size_t)n * 1024 + k - 1024);
               v.x = -v.x; v.y = -v.y; v.z = -v.z; v.w = -v.w; }
    } else {
        if (k < 1024) v = *(const float4*)(wim + (size_t)n * 1024 + k);
        else          v = *(const float4*)(wre + (size_t)n * 1024 + k - 1024);
    }
    v.x = tf32f(v.x); v.y = tf32f(v.y); v.z = tf32f(v.z); v.w = tf32f(v.w);
    *(float4*)(g_OWB + (size_t)i * 4) = v;
}

// ---------------- K1: in-projection (128x128 tiles, 256 thr, 2 CTA/SM) -----
__global__ void __launch_bounds__(256, 2) proj_kernel(
    const float* __restrict__ Bre, const float* __restrict__ Bim)
{
    extern __shared__ float smem[];
    float acc[4][4][4] = {};
    const int m0 = blockIdx.y << 7;
    const int n0 = blockIdx.x << 7;   // augmented col base
    auto la = [&](int row, int f4) -> const void* {
        return (const void*)(g_XA + (size_t)(m0 + row) * 2048 + (f4 << 2));
    };
    auto lb = [&](int row, int f4) -> const void* {
        return (const void*)(g_WB + (size_t)(n0 + row) * 2048 + (f4 << 2));
    };
    gemm_cp(la, lb, 64, acc, smem);

    FRAG_256;
    #pragma unroll
    for (int i = 0; i < 4; i++) {
        #pragma unroll
        for (int j = 0; j < 4; j++) {
            int na = n0 + wn + j * 8 + 2 * tg;    // even
            int n = na >> 1;
            int sect = n >> 10, e = n & 1023;
            int bh_base = (e >> 6), d = e & 63;
            float bre = Bre[n], bim = Bim[n];
            #pragma unroll
            for (int rr = 0; rr < 2; rr++) {
                int m = m0 + wm + i * 16 + g + rr * 8;
                float re = acc[i][j][rr * 2 + 0] + bre;
                float im = acc[i][j][rr * 2 + 1] + bim;
                int t = m >> 2, b = m & 3;
                int bh = b * 16 + bh_base;
                if (sect == 0) {
                    int idx = (bh * 1024 + t) * 128 + d;
                    g_Q[idx] = tf32f(re * 0.125f); g_Q[idx + 64] = tf32f(im * 0.125f);
                } else if (sect == 1) {
                    int idx = (bh * 1024 + t) * 128 + d;
                    g_K2[idx] = tf32f(re + im); g_K2[idx + 64] = tf32f(re - im);
                } else {
                    int idx = (bh * 128 + d) * 1024 + t;
                    g_VT[idx] = tf32f(re); g_VT[idx + 65536] = tf32f(im);
                }
            }
        }
    }
}

// ---------------- K1b: per-head V column sums ----------------
__global__ void vsum_kernel() {
    int rowid = blockIdx.x * 8 + (threadIdx.x >> 5);   // 0..8191
    int lane = threadIdx.x & 31;
    const float* p = g_VT + (size_t)rowid * T_DIM;
    float s = 0.f;
    for (int t = lane; t < T_DIM; t += 32) s += p[t];
    #pragma unroll
    for (int o = 16; o; o >>= 1) s += __shfl_xor_sync(0xFFFFFFFFu, s, o);
    if (!lane) g_VSUM[rowid] = s;
}

// ---------------- K2: batched QK^T + global min/max ----------------
__global__ void __launch_bounds__(256, 2) qk_kernel()
{
    extern __shared__ float smem[];
    __shared__ unsigned sMin[8], sMax[8];
    float acc[4][4][4] = {};
    const int bh = blockIdx.z;
    const int m0 = blockIdx.y << 7, n0 = blockIdx.x << 7;
    const float* Qp = g_Q  + (size_t)bh * T_DIM * 128;
    const float* Kp = g_K2 + (size_t)bh * T_DIM * 128;
    auto la = [&](int row, int f4) -> const void* {
        return (const void*)(Qp + (size_t)(m0 + row) * 128 + (f4 << 2));
    };
    auto lb = [&](int row, int f4) -> const void* {
        return (const void*)(Kp + (size_t)(n0 + row) * 128 + (f4 << 2));
    };
    gemm_cp(la, lb, 4, acc, smem);

    FRAG_256;
    float* out = g_AWR + (size_t)bh * T_DIM * T_DIM;
    unsigned umin = 0xFFFFFFFFu, umax = 0u;
    #pragma unroll
    for (int i = 0; i < 4; i++) {
        #pragma unroll
        for (int j = 0; j < 4; j++) {
            int n = n0 + wn + j * 8 + 2 * tg;
            #pragma unroll
            for (int rr = 0; rr < 2; rr++) {
                int m = m0 + wm + i * 16 + g + rr * 8;
                float v0 = tf32f(acc[i][j][rr * 2 + 0]);   // store pre-rounded
                float v1 = tf32f(acc[i][j][rr * 2 + 1]);
                *(float2*)(out + (size_t)m * T_DIM + n) = make_float2(v0, v1);
                unsigned e0 = encodeOrd(v0), e1 = encodeOrd(v1);
                umin = min(umin, min(e0, e1));
                umax = max(umax, max(e0, e1));
            }
        }
    }
    #pragma unroll
    for (int o = 16; o; o >>= 1) {
        umin = min(umin, __shfl_xor_sync(0xFFFFFFFFu, umin, o));
        umax = max(umax, __shfl_xor_sync(0xFFFFFFFFu, umax, o));
    }
    if (!lane) { sMin[warp] = umin; sMax[warp] = umax; }
    __syncthreads();
    if (threadIdx.x == 0) {
        umin = sMin[0]; umax = sMax[0];
        #pragma unroll
        for (int w = 1; w < 8; w++) { umin = min(umin, sMin[w]); umax = max(umax, sMax[w]); }
        atomicMin(&g_minU, umin);
        atomicMax(&g_maxU, umax);
    }
}

// ---------------- K3: AV with fused normalization ----------------
__global__ void __launch_bounds__(256, 2) attn_kernel()
{
    extern __shared__ float smem[];
    float acc[4][4][4] = {};
    const int m0 = blockIdx.x << 7;
    const int bh = blockIdx.y;
    const float* A = g_AWR + ((size_t)bh << 20);
    const float* V = g_VT + (size_t)bh * 128 * T_DIM;
    auto la = [&](int row, int f4) -> const void* {
        return (const void*)(A + (size_t)(m0 + row) * 1024 + (f4 << 2));
    };
    auto lb = [&](int row, int f4) -> const void* {
        return (const void*)(V + (size_t)row * 1024 + (f4 << 2));
    };
    gemm_cp(la, lb, 32, acc, smem);

    FRAG_256;
    float gmin = decodeOrd(g_minU);
    float gmax = decodeOrd(g_maxU);
    float inv = 1.0f / (gmax - gmin);
    int b = bh >> 4, h = bh & 15;
    #pragma unroll
    for (int i = 0; i < 4; i++) {
        #pragma unroll
        for (int j = 0; j < 4; j++) {
            int dd = wn + j * 8 + 2 * tg;     // even, 0..126
            float vs0 = g_VSUM[bh * 128 + dd];
            float vs1 = g_VSUM[bh * 128 + dd + 1];
            int col0 = (dd < 64)     ? h * 64 + dd     : 1024 + h * 64 + dd - 64;
            int col1 = (dd + 1 < 64) ? h * 64 + dd + 1 : 1024 + h * 64 + dd + 1 - 64;
            #pragma unroll
            for (int rr = 0; rr < 2; rr++) {
                int t = m0 + wm + i * 16 + g + rr * 8;
                int m2 = t * B_DIM + b;
                float v0 = (acc[i][j][rr * 2 + 0] - gmin * vs0) * inv;
                float v1 = (acc[i][j][rr * 2 + 1] - gmin * vs1) * inv;
                g_AT2[(size_t)m2 * 2048 + col0] = tf32f(v0);
                g_AT2[(size_t)m2 * 2048 + col1] = tf32f(v1);
            }
        }
    }
}

// ---------------- K4: head-averaged attention map ----------------
__global__ void avg_kernel(float* __restrict__ out)
{
    int idx = blockIdx.x * blockDim.x + threadIdx.x;
    int b = idx >> 20;
    int off = idx & 0xFFFFF;
    const float* base = g_AWR + ((size_t)b << 24) + off;
    float s = 0.f;
    #pragma unroll
    for (int h = 0; h < 16; h++) s += base[(size_t)h << 20];
    float gmin = decodeOrd(g_minU);
    float gmax = decodeOrd(g_maxU);
    out[idx] = (s * (1.0f / 16.0f) - gmin) / (gmax - gmin);
}

// ---------------- K5: out-projection (128x128, 256 thr, 2 CTA/SM) ----------
__global__ void __launch_bounds__(256, 2) outproj_kernel(
    const float* __restrict__ obre, const float* __restrict__ obim,
    float* __restrict__ outRe, float* __restrict__ outIm)
{
    extern __shared__ float smem[];
    float acc[4][4][4] = {};
    const int m0 = blockIdx.y << 7;
    const int n0 = blockIdx.x << 7;   // augmented (0..2047)
    auto la = [&](int row, int f4) -> const void* {
        return (const void*)(g_AT2 + (size_t)(m0 + row) * 2048 + (f4 << 2));
    };
    auto lb = [&](int row, int f4) -> const void* {
        return (const void*)(g_OWB + (size_t)(n0 + row) * 2048 + (f4 << 2));
    };
    gemm_cp(la, lb, 64, acc, smem);

    FRAG_256;
    #pragma unroll
    for (int i = 0; i < 4; i++) {
        #pragma unroll
        for (int j = 0; j < 4; j++) {
            int na = n0 + wn + j * 8 + 2 * tg;
            int n = na >> 1;
            float bre = obre[n], bim = obim[n];
            #pragma unroll
            for (int rr = 0; rr < 2; rr++) {
                int m = m0 + wm + i * 16 + g + rr * 8;
                outRe[(size_t)m * 1024 + n] = acc[i][j][rr * 2 + 0] + bre;
                outIm[(size_t)m * 1024 + n] = acc[i][j][rr * 2 + 1] + bim;
            }
        }
    }
}

// ---------------- launch ----------------
#define SMEM_G (3 * 256 * 128)   // 98304

extern "C" void kernel_launch(void* const* d_in, const int* in_sizes, int n_in,
                              void* d_out, int out_size)
{
    const float* x_re  = (const float*)d_in[0];
    const float* x_im  = (const float*)d_in[1];
    const float* w_re  = (const float*)d_in[2];
    const float* w_im  = (const float*)d_in[3];
    const float* b_re  = (const float*)d_in[4];
    const float* b_im  = (const float*)d_in[5];
    const float* ow_re = (const float*)d_in[6];
    const float* ow_im = (const float*)d_in[7];
    const float* ob_re = (const float*)d_in[8];
    const float* ob_im = (const float*)d_in[9];

    float* out_re = (float*)d_out;
    float* out_im = out_re + (size_t)MROWS * E_DIM;
    float* aw_avg = out_im + (size_t)MROWS * E_DIM;

    cudaFuncSetAttribute(proj_kernel,    cudaFuncAttributeMaxDynamicSharedMemorySize, SMEM_G);
    cudaFuncSetAttribute(outproj_kernel, cudaFuncAttributeMaxDynamicSharedMemorySize, SMEM_G);
    cudaFuncSetAttribute(qk_kernel,      cudaFuncAttributeMaxDynamicSharedMemorySize, SMEM_G);
    cudaFuncSetAttribute(attn_kernel,    cudaFuncAttributeMaxDynamicSharedMemorySize, SMEM_G);

    init_kernel<<<1, 1>>>();
    pack_x_kernel <<<8192, 256>>>(x_re, x_im);
    pack_w_kernel <<<12288, 256>>>(w_re, w_im);
    pack_ow_kernel<<<4096, 256>>>(ow_re, ow_im);

    proj_kernel<<<dim3(48, 32), 256, SMEM_G>>>(b_re, b_im);
    vsum_kernel<<<1024, 256>>>();
    qk_kernel<<<dim3(8, 8, 64), 256, SMEM_G>>>();
    attn_kernel<<<dim3(8, 64), 256, SMEM_G>>>();
    avg_kernel<<<(B_DIM * T_DIM * T_DIM) / 256, 256>>>(aw_avg);
    outproj_kernel<<<dim3(16, 32), 256, SMEM_G>>>(ob_re, ob_im, out_re, out_im);
}

// round 17
// speedup vs baseline: 2.7960x; 1.1164x over previous
#include <cuda_runtime.h>
#include <cuda_fp16.h>
#include <cstdint>

#define T_DIM 1024
#define B_DIM 4
#define E_DIM 1024
#define NBH   64
#define MROWS 4096

// ---------------- scratch (all GEMM operands fp16) ----------------
__device__ __half g_XA [MROWS * 2048];                 // packed aug X        16MB
__device__ __half g_WB [6144 * 2048];                  // packed aug W        25MB
__device__ __half g_OWB[2048 * 2048];                  // packed aug OW        8MB
__device__ __half g_Q  [NBH * T_DIM * 128];            // [qre*s | qim*s]     16MB
__device__ __half g_K2 [NBH * T_DIM * 128];            // [kp | km]           16MB
__device__ __half g_VT [NBH * 128 * T_DIM];            // [vre ; vim] transp  16MB
__device__ __half g_AT2[MROWS * 2048];                 // attn out augmented  16MB
__device__ __half g_AWR[(size_t)NBH * T_DIM * T_DIM];  // raw scores         128MB
__device__ float  g_VSUM[NBH * 128];
__device__ unsigned g_minU, g_maxU;

// ---------------- helpers ----------------
__device__ __forceinline__ unsigned encodeOrd(float f) {
    unsigned u = __float_as_uint(f);
    return (u & 0x80000000u) ? ~u : (u | 0x80000000u);
}
__device__ __forceinline__ float decodeOrd(unsigned u) {
    return (u & 0x80000000u) ? __uint_as_float(u & 0x7FFFFFFFu)
                             : __uint_as_float(~u);
}
__device__ __forceinline__ uint32_t h2u(float a, float b) {
    __half2 h = __floats2half2_rn(a, b);
    return *(uint32_t*)&h;
}
__device__ __forceinline__ uint32_t smem_u32(const void* p) {
    uint32_t a;
    asm("{ .reg .u64 t; cvta.to.shared.u64 t, %1; cvt.u32.u64 %0, t; }"
        : "=r"(a) : "l"(p));
    return a;
}
__device__ __forceinline__ void mma16(float* c, const uint32_t* a, const uint32_t* b) {
    asm volatile(
        "mma.sync.aligned.m16n8k16.row.col.f32.f16.f16.f32 "
        "{%0,%1,%2,%3}, {%4,%5,%6,%7}, {%8,%9}, {%0,%1,%2,%3};"
        : "+f"(c[0]), "+f"(c[1]), "+f"(c[2]), "+f"(c[3])
        : "r"(a[0]), "r"(a[1]), "r"(a[2]), "r"(a[3]), "r"(b[0]), "r"(b[1]));
}
__device__ __forceinline__ void cpa16(uint32_t dst, const void* src) {
    asm volatile("cp.async.cg.shared.global [%0], [%1], 16;"
                 :: "r"(dst), "l"(src) : "memory");
}
__device__ __forceinline__ void cpa_commit() {
    asm volatile("cp.async.commit_group;" ::: "memory");
}
template<int N> __device__ __forceinline__ void cpa_wait() {
    asm volatile("cp.async.wait_group %0;" :: "n"(N) : "memory");
}

__global__ void init_kernel() { g_minU = 0xFFFFFFFFu; g_maxU = 0u; }

// ---------------- cp.async 3-stage fp16 GEMM core ----------------
// C(128x128) = A(128xK) * B(128xK)^T ; chunk = 64 halves of K; 256 threads.
// Rows 128B (64 halves), float4-granular XOR swizzle. Lambdas take
// (row, u8) where u8 indexes 16B (8-half) groups along K.
template<class LA, class LB>
__device__ __forceinline__ void gemm_cp(const LA& la, const LB& lb, int nChunks,
                                        float (&acc)[4][4][4], char* smem)
{
    const int tid  = threadIdx.x;
    const int lane = tid & 31;
    const int warp = tid >> 5;
    const int g = lane >> 2, tg = lane & 3;
    const int wm = (warp >> 2) * 64;
    const int wn = (warp & 3) * 32;
    constexpr int STAGEB = 256 * 128;            // bytes per stage
    const uint32_t sb = smem_u32(smem);

    auto produce = [&](int ch) {
        uint32_t aB = sb + (uint32_t)(ch % 3) * STAGEB;
        uint32_t bB = aB + 128 * 128;
        #pragma unroll
        for (int t = 0; t < 4; t++) {
            int idx = tid + t * 256;
            int row = idx >> 3, c4 = idx & 7;
            cpa16(aB + (uint32_t)((row * 8 + (c4 ^ (row & 7))) * 16),
                  la(row, ch * 8 + c4));
        }
        #pragma unroll
        for (int t = 0; t < 4; t++) {
            int idx = tid + t * 256;
            int row = idx >> 3, c4 = idx & 7;
            cpa16(bB + (uint32_t)((row * 8 + (c4 ^ (row & 7))) * 16),
                  lb(row, ch * 8 + c4));
        }
    };

    produce(0); cpa_commit();
    if (nChunks > 1) produce(1);
    cpa_commit();

    for (int ch = 0; ch < nChunks; ch++) {
        cpa_wait<1>();
        __syncthreads();
        const char* As = smem + (ch % 3) * STAGEB;
        const char* Bs = As + 128 * 128;
        if (ch + 2 < nChunks) produce(ch + 2);
        cpa_commit();
        #pragma unroll
        for (int ks = 0; ks < 4; ks++) {
            const int y0 = ((2 * ks)     ^ g) * 16 + 4 * tg;
            const int y1 = ((2 * ks + 1) ^ g) * 16 + 4 * tg;
            uint32_t af[4][4], bf[4][2];
            #pragma unroll
            for (int i = 0; i < 4; i++) {
                const char* pm = As + (wm + i * 16 + g) * 128;
                af[i][0] = *(const uint32_t*)(pm + y0);
                af[i][1] = *(const uint32_t*)(pm + 1024 + y0);   // +8 rows
                af[i][2] = *(const uint32_t*)(pm + y1);
                af[i][3] = *(const uint32_t*)(pm + 1024 + y1);
            }
            #pragma unroll
            for (int j = 0; j < 4; j++) {
                const char* pn = Bs + (wn + j * 8 + g) * 128;
                bf[j][0] = *(const uint32_t*)(pn + y0);
                bf[j][1] = *(const uint32_t*)(pn + y1);
            }
            #pragma unroll
            for (int i = 0; i < 4; i++)
                #pragma unroll
                for (int j = 0; j < 4; j++)
                    mma16(acc[i][j], af[i], bf[j]);
        }
    }
}

#define FRAG_256 \
    const int lane = threadIdx.x & 31; const int warp = threadIdx.x >> 5; \
    const int wm = (warp >> 2) * 64, wn = (warp & 3) * 32; \
    const int g = lane >> 2, tg = lane & 3;

// ---------------- packing kernels (augmented, fp32 -> fp16) ---------------
__global__ void pack_x_kernel(const float* __restrict__ xre,
                              const float* __restrict__ xim) {
    int i = blockIdx.x * 256 + threadIdx.x;     // 8-half group over 4096*256
    int m = i >> 8, grp = i & 255;
    int k = grp << 3;
    const float* s = (k < 1024) ? (xre + (size_t)m * 1024 + k)
                                : (xim + (size_t)m * 1024 + k - 1024);
    float4 v0 = *(const float4*)s, v1 = *(const float4*)(s + 4);
    uint4 o = { h2u(v0.x, v0.y), h2u(v0.z, v0.w), h2u(v1.x, v1.y), h2u(v1.z, v1.w) };
    *(uint4*)(g_XA + (size_t)i * 8) = o;
}
__global__ void pack_w_kernel(const float* __restrict__ wre,
                              const float* __restrict__ wim) {
    int i = blockIdx.x * 256 + threadIdx.x;     // 8-half group over 6144*256
    int row = i >> 8, grp = i & 255;
    int n = row >> 1, p = row & 1;
    int k = grp << 3;
    const float* s;
    float sgn = 1.f;
    if (p == 0) {
        if (k < 1024) s = wre + (size_t)n * 1024 + k;
        else { s = wim + (size_t)n * 1024 + k - 1024; sgn = -1.f; }
    } else {
        s = (k < 1024) ? (wim + (size_t)n * 1024 + k)
                       : (wre + (size_t)n * 1024 + k - 1024);
    }
    float4 v0 = *(const float4*)s, v1 = *(const float4*)(s + 4);
    uint4 o = { h2u(sgn*v0.x, sgn*v0.y), h2u(sgn*v0.z, sgn*v0.w),
                h2u(sgn*v1.x, sgn*v1.y), h2u(sgn*v1.z, sgn*v1.w) };
    *(uint4*)(g_WB + (size_t)i * 8) = o;
}
__global__ void pack_ow_kernel(const float* __restrict__ wre,
                               const float* __restrict__ wim) {
    int i = blockIdx.x * 256 + threadIdx.x;     // 8-half group over 2048*256
    int row = i >> 8, grp = i & 255;
    int n = row >> 1, p = row & 1;
    int k = grp << 3;
    const float* s;
    float sgn = 1.f;
    if (p == 0) {
        if (k < 1024) s = wre + (size_t)n * 1024 + k;
        else { s = wim + (size_t)n * 1024 + k - 1024; sgn = -1.f; }
    } else {
        s = (k < 1024) ? (wim + (size_t)n * 1024 + k)
                       : (wre + (size_t)n * 1024 + k - 1024);
    }
    float4 v0 = *(const float4*)s, v1 = *(const float4*)(s + 4);
    uint4 o = { h2u(sgn*v0.x, sgn*v0.y), h2u(sgn*v0.z, sgn*v0.w),
                h2u(sgn*v1.x, sgn*v1.y), h2u(sgn*v1.z, sgn*v1.w) };
    *(uint4*)(g_OWB + (size_t)i * 8) = o;
}

// ---------------- K1: in-projection ----------------
__global__ void __launch_bounds__(256, 2) proj_kernel(
    const float* __restrict__ Bre, const float* __restrict__ Bim)
{
    extern __shared__ char smem[];
    float acc[4][4][4] = {};
    const int m0 = blockIdx.y << 7;
    const int n0 = blockIdx.x << 7;   // augmented col base
    auto la = [&](int row, int u8) -> const void* {
        return (const void*)(g_XA + (size_t)(m0 + row) * 2048 + (u8 << 3));
    };
    auto lb = [&](int row, int u8) -> const void* {
        return (const void*)(g_WB + (size_t)(n0 + row) * 2048 + (u8 << 3));
    };
    gemm_cp(la, lb, 32, acc, smem);

    FRAG_256;
    #pragma unroll
    for (int i = 0; i < 4; i++) {
        #pragma unroll
        for (int j = 0; j < 4; j++) {
            int na = n0 + wn + j * 8 + 2 * tg;    // even
            int n = na >> 1;
            int sect = n >> 10, e = n & 1023;
            int bh_base = (e >> 6), d = e & 63;
            float bre = Bre[n], bim = Bim[n];
            #pragma unroll
            for (int rr = 0; rr < 2; rr++) {
                int m = m0 + wm + i * 16 + g + rr * 8;
                float re = acc[i][j][rr * 2 + 0] + bre;
                float im = acc[i][j][rr * 2 + 1] + bim;
                int t = m >> 2, b = m & 3;
                int bh = b * 16 + bh_base;
                if (sect == 0) {
                    int idx = (bh * 1024 + t) * 128 + d;
                    g_Q[idx]      = __float2half_rn(re * 0.125f);
                    g_Q[idx + 64] = __float2half_rn(im * 0.125f);
                } else if (sect == 1) {
                    int idx = (bh * 1024 + t) * 128 + d;
                    g_K2[idx]      = __float2half_rn(re + im);
                    g_K2[idx + 64] = __float2half_rn(re - im);
                } else {
                    int idx = (bh * 128 + d) * 1024 + t;
                    g_VT[idx]         = __float2half_rn(re);
                    g_VT[idx + 65536] = __float2half_rn(im);
                }
            }
        }
    }
}

// ---------------- K1b: per-head V column sums ----------------
__global__ void vsum_kernel() {
    int rowid = blockIdx.x * 8 + (threadIdx.x >> 5);   // 0..8191
    int lane = threadIdx.x & 31;
    const __half* p = g_VT + (size_t)rowid * T_DIM;
    float s = 0.f;
    for (int t = lane; t < T_DIM; t += 32) s += __half2float(p[t]);
    #pragma unroll
    for (int o = 16; o; o >>= 1) s += __shfl_xor_sync(0xFFFFFFFFu, s, o);
    if (!lane) g_VSUM[rowid] = s;
}

// ---------------- K2: batched QK^T + global min/max ----------------
__global__ void __launch_bounds__(256, 2) qk_kernel()
{
    extern __shared__ char smem[];
    __shared__ unsigned sMin[8], sMax[8];
    float acc[4][4][4] = {};
    const int bh = blockIdx.z;
    const int m0 = blockIdx.y << 7, n0 = blockIdx.x << 7;
    const __half* Qp = g_Q  + (size_t)bh * T_DIM * 128;
    const __half* Kp = g_K2 + (size_t)bh * T_DIM * 128;
    auto la = [&](int row, int u8) -> const void* {
        return (const void*)(Qp + (size_t)(m0 + row) * 128 + (u8 << 3));
    };
    auto lb = [&](int row, int u8) -> const void* {
        return (const void*)(Kp + (size_t)(n0 + row) * 128 + (u8 << 3));
    };
    gemm_cp(la, lb, 2, acc, smem);

    FRAG_256;
    __half* out = g_AWR + (size_t)bh * T_DIM * T_DIM;
    unsigned umin = 0xFFFFFFFFu, umax = 0u;
    #pragma unroll
    for (int i = 0; i < 4; i++) {
        #pragma unroll
        for (int j = 0; j < 4; j++) {
            int n = n0 + wn + j * 8 + 2 * tg;
            #pragma unroll
            for (int rr = 0; rr < 2; rr++) {
                int m = m0 + wm + i * 16 + g + rr * 8;
                __half h0 = __float2half_rn(acc[i][j][rr * 2 + 0]);
                __half h1 = __float2half_rn(acc[i][j][rr * 2 + 1]);
                *(__half2*)(out + (size_t)m * T_DIM + n) = __halves2half2(h0, h1);
                unsigned e0 = encodeOrd(__half2float(h0));
                unsigned e1 = encodeOrd(__half2float(h1));
                umin = min(umin, min(e0, e1));
                umax = max(umax, max(e0, e1));
            }
        }
    }
    #pragma unroll
    for (int o = 16; o; o >>= 1) {
        umin = min(umin, __shfl_xor_sync(0xFFFFFFFFu, umin, o));
        umax = max(umax, __shfl_xor_sync(0xFFFFFFFFu, umax, o));
    }
    if (!lane) { sMin[warp] = umin; sMax[warp] = umax; }
    __syncthreads();
    if (threadIdx.x == 0) {
        umin = sMin[0]; umax = sMax[0];
        #pragma unroll
        for (int w = 1; w < 8; w++) { umin = min(umin, sMin[w]); umax = max(umax, sMax[w]); }
        atomicMin(&g_minU, umin);
        atomicMax(&g_maxU, umax);
    }
}

// ---------------- K3: AV with fused normalization ----------------
__global__ void __launch_bounds__(256, 2) attn_kernel()
{
    extern __shared__ char smem[];
    float acc[4][4][4] = {};
    const int m0 = blockIdx.x << 7;
    const int bh = blockIdx.y;
    const __half* A = g_AWR + ((size_t)bh << 20);
    const __half* V = g_VT + (size_t)bh * 128 * T_DIM;
    auto la = [&](int row, int u8) -> const void* {
        return (const void*)(A + (size_t)(m0 + row) * 1024 + (u8 << 3));
    };
    auto lb = [&](int row, int u8) -> const void* {
        return (const void*)(V + (size_t)row * 1024 + (u8 << 3));
    };
    gemm_cp(la, lb, 16, acc, smem);

    FRAG_256;
    float gmin = decodeOrd(g_minU);
    float gmax = decodeOrd(g_maxU);
    float inv = 1.0f / (gmax - gmin);
    int b = bh >> 4, h = bh & 15;
    #pragma unroll
    for (int i = 0; i < 4; i++) {
        #pragma unroll
        for (int j = 0; j < 4; j++) {
            int dd = wn + j * 8 + 2 * tg;     // even, 0..126
            float vs0 = g_VSUM[bh * 128 + dd];
            float vs1 = g_VSUM[bh * 128 + dd + 1];
            int col0 = (dd < 64)     ? h * 64 + dd     : 1024 + h * 64 + dd - 64;
            int col1 = (dd + 1 < 64) ? h * 64 + dd + 1 : 1024 + h * 64 + dd + 1 - 64;
            #pragma unroll
            for (int rr = 0; rr < 2; rr++) {
                int t = m0 + wm + i * 16 + g + rr * 8;
                int m2 = t * B_DIM + b;
                float v0 = (acc[i][j][rr * 2 + 0] - gmin * vs0) * inv;
                float v1 = (acc[i][j][rr * 2 + 1] - gmin * vs1) * inv;
                g_AT2[(size_t)m2 * 2048 + col0] = __float2half_rn(v0);
                g_AT2[(size_t)m2 * 2048 + col1] = __float2half_rn(v1);
            }
        }
    }
}

// ---------------- K4: head-averaged attention map ----------------
__global__ void avg_kernel(float* __restrict__ out)
{
    int idx = blockIdx.x * blockDim.x + threadIdx.x;
    int b = idx >> 20;
    int off = idx & 0xFFFFF;
    const __half* base = g_AWR + ((size_t)b << 24) + off;
    float s = 0.f;
    #pragma unroll
    for (int h = 0; h < 16; h++) s += __half2float(base[(size_t)h << 20]);
    float gmin = decodeOrd(g_minU);
    float gmax = decodeOrd(g_maxU);
    out[idx] = (s * (1.0f / 16.0f) - gmin) / (gmax - gmin);
}

// ---------------- K5: out-projection ----------------
__global__ void __launch_bounds__(256, 2) outproj_kernel(
    const float* __restrict__ obre, const float* __restrict__ obim,
    float* __restrict__ outRe, float* __restrict__ outIm)
{
    extern __shared__ char smem[];
    float acc[4][4][4] = {};
    const int m0 = blockIdx.y << 7;
    const int n0 = blockIdx.x << 7;   // augmented (0..2047)
    auto la = [&](int row, int u8) -> const void* {
        return (const void*)(g_AT2 + (size_t)(m0 + row) * 2048 + (u8 << 3));
    };
    auto lb = [&](int row, int u8) -> const void* {
        return (const void*)(g_OWB + (size_t)(n0 + row) * 2048 + (u8 << 3));
    };
    gemm_cp(la, lb, 32, acc, smem);

    FRAG_256;
    #pragma unroll
    for (int i = 0; i < 4; i++) {
        #pragma unroll
        for (int j = 0; j < 4; j++) {
            int na = n0 + wn + j * 8 + 2 * tg;
            int n = na >> 1;
            float bre = obre[n], bim = obim[n];
            #pragma unroll
            for (int rr = 0; rr < 2; rr++) {
                int m = m0 + wm + i * 16 + g + rr * 8;
                outRe[(size_t)m * 1024 + n] = acc[i][j][rr * 2 + 0] + bre;
                outIm[(size_t)m * 1024 + n] = acc[i][j][rr * 2 + 1] + bim;
            }
        }
    }
}

// ---------------- launch ----------------
#define SMEM_G (3 * 256 * 128)   // 98304 bytes

extern "C" void kernel_launch(void* const* d_in, const int* in_sizes, int n_in,
                              void* d_out, int out_size)
{
    const float* x_re  = (const float*)d_in[0];
    const float* x_im  = (const float*)d_in[1];
    const float* w_re  = (const float*)d_in[2];
    const float* w_im  = (const float*)d_in[3];
    const float* b_re  = (const float*)d_in[4];
    const float* b_im  = (const float*)d_in[5];
    const float* ow_re = (const float*)d_in[6];
    const float* ow_im = (const float*)d_in[7];
    const float* ob_re = (const float*)d_in[8];
    const float* ob_im = (const float*)d_in[9];

    float* out_re = (float*)d_out;
    float* out_im = out_re + (size_t)MROWS * E_DIM;
    float* aw_avg = out_im + (size_t)MROWS * E_DIM;

    cudaFuncSetAttribute(proj_kernel,    cudaFuncAttributeMaxDynamicSharedMemorySize, SMEM_G);
    cudaFuncSetAttribute(outproj_kernel, cudaFuncAttributeMaxDynamicSharedMemorySize, SMEM_G);
    cudaFuncSetAttribute(qk_kernel,      cudaFuncAttributeMaxDynamicSharedMemorySize, SMEM_G);
    cudaFuncSetAttribute(attn_kernel,    cudaFuncAttributeMaxDynamicSharedMemorySize, SMEM_G);

    init_kernel<<<1, 1>>>();
    pack_x_kernel <<<4096, 256>>>(x_re, x_im);
    pack_w_kernel <<<6144, 256>>>(w_re, w_im);
    pack_ow_kernel<<<2048, 256>>>(ow_re, ow_im);

    proj_kernel<<<dim3(48, 32), 256, SMEM_G>>>(b_re, b_im);
    vsum_kernel<<<1024, 256>>>();
    qk_kernel<<<dim3(8, 8, 64), 256, SMEM_G>>>();
    attn_kernel<<<dim3(8, 64), 256, SMEM_G>>>();
    avg_kernel<<<(B_DIM * T_DIM * T_DIM) / 256, 256>>>(aw_avg);
    outproj_kernel<<<dim3(16, 32), 256, SMEM_G>>>(ob_re, ob_im, out_re, out_im);
}